// round 1
// baseline (speedup 1.0000x reference)
#include <cuda_runtime.h>
#include <cstdint>

// ---------------------------------------------------------------------------
// SLAYER SNN pipeline, t-major intermediates:
//   K0 : pool4 input (n,c,256,256,t) -> p0 (n,t,2,64,64)   [transpose to t-major]
//   K1a: conv1 7x7 pad3 (2->4) per (n,t) slab -> u1 (n,t,4,64,64)   [f32x2 FMA]
//   K1b: spike scan over t (per location) + fused 4x4 pool -> p1 (n,t,4,16,16)
//   K2a: conv2 7x7 pad3 (4->8) per (n,t) slab -> u2 (n,t,8,16,16)
//   K2b: spike scan over t -> s2 (n,t,8,16,16) uint8
//   K3 : 4x4 pool + einsum with wl -> out (n,2,t)
// ---------------------------------------------------------------------------

#define NB 4
#define TT 100

__device__ float g_p0[NB*TT*2*64*64];          // 3,276,800 floats
__device__ float g_u1[NB*TT*4*64*64];          // 6,553,600 floats
__device__ float g_p1[NB*TT*4*16*16];          //   409,600 floats
__device__ float g_u2[NB*TT*8*16*16];          //   819,200 floats
__device__ unsigned char g_s2[NB*TT*8*16*16];  //   819,200 bytes

__constant__ float c_w0[4*2*7*7];    // 392
__constant__ float c_w1[8*4*7*7];    // 1568
__constant__ float c_wl[2*8*4*4];    // 256

// ---- packed f32x2 helpers (sm_100+) ----
__device__ __forceinline__ unsigned long long pack2(float lo, float hi) {
    unsigned long long r;
    asm("mov.b64 %0, {%1, %2};" : "=l"(r) : "f"(lo), "f"(hi));
    return r;
}
__device__ __forceinline__ void unpack2(unsigned long long v, float& lo, float& hi) {
    asm("mov.b64 {%0, %1}, %2;" : "=f"(lo), "=f"(hi) : "l"(v));
}
__device__ __forceinline__ unsigned long long fma2(unsigned long long a,
                                                   unsigned long long b,
                                                   unsigned long long c) {
    unsigned long long d;
    asm("fma.rn.f32x2 %0, %1, %2, %3;" : "=l"(d) : "l"(a), "l"(b), "l"(c));
    return d;
}

// ---------------------------------------------------------------------------
// K0: 4x4 average pool of raw input with layout transpose to t-major.
// grid: 512 blocks = (n,c,H64), 256 threads. Reads 210MB coalesced (float4
// over t), writes p0 (n,t,c,64,64) coalesced via smem transpose.
// ---------------------------------------------------------------------------
__global__ void __launch_bounds__(256) k0_pool(const float* __restrict__ in) {
    const int b = blockIdx.x;
    const int n = b >> 7, c = (b >> 6) & 1, H = b & 63;
    __shared__ float sm[TT][65];   // [t][W]

    const float* base = in + (size_t)((n*2 + c)*256 + H*4) * 25600;  // h stride 256*100

    for (int idx = threadIdx.x; idx < 1600; idx += 256) {
        int W  = idx / 25;
        int tq = idx - W*25;           // t-quad 0..24
        const float4* p = (const float4*)(base + (size_t)(W*4)*100 + tq*4);
        float4 s = make_float4(0.f, 0.f, 0.f, 0.f);
#pragma unroll
        for (int dy = 0; dy < 4; dy++)
#pragma unroll
            for (int dx = 0; dx < 4; dx++) {
                float4 v = p[dy*6400 + dx*25];   // (dy*25600+dx*100)/4
                s.x += v.x; s.y += v.y; s.z += v.z; s.w += v.w;
            }
        int t = tq*4;
        sm[t+0][W] = s.x*0.0625f; sm[t+1][W] = s.y*0.0625f;
        sm[t+2][W] = s.z*0.0625f; sm[t+3][W] = s.w*0.0625f;
    }
    __syncthreads();
    const size_t ob = ((size_t)(n*TT)*2 + c)*4096 + H*64;
    for (int idx = threadIdx.x; idx < 6400; idx += 256) {
        int t = idx >> 6, W = idx & 63;
        g_p0[ob + (size_t)t*8192 + W] = sm[t][W];
    }
}

// ---------------------------------------------------------------------------
// K1a: conv1 2->4ch 7x7 pad3 on 64x64, one (n,t) slab per block, 256 threads.
// Inner loop in packed f32x2 (2 output pixels per FMA). Weights from constant.
// ---------------------------------------------------------------------------
__global__ void __launch_bounds__(256, 2) k1a_conv1() {
    const int b = blockIdx.x;              // n*100 + t
    __shared__ float si[2*70*71];          // zero-padded input, stride 71

    for (int i = threadIdx.x; i < 2*70*71; i += 256) si[i] = 0.f;
    __syncthreads();
    const float* slab = g_p0 + (size_t)b * 8192;
    for (int i = threadIdx.x; i < 8192; i += 256) {
        int ci = i >> 12, h = (i >> 6) & 63, w = i & 63;
        si[ci*4970 + (h+3)*71 + (w+3)] = slab[i];
    }
    __syncthreads();

    float* out = g_u1 + (size_t)b * 16384;

#pragma unroll 1
    for (int rep = 0; rep < 2; rep++) {
        const int pos = threadIdx.x + (rep << 8);   // 0..511
        const int h  = pos >> 3;
        const int ws = (pos & 7) << 3;              // 8-pixel segment start
        unsigned long long acc[4][4];
#pragma unroll
        for (int o = 0; o < 4; o++)
#pragma unroll
            for (int k = 0; k < 4; k++) acc[o][k] = 0ull;

#pragma unroll 1
        for (int ci = 0; ci < 2; ci++) {
#pragma unroll 1
            for (int dy = 0; dy < 7; dy++) {
                const float* r = si + ci*4970 + (h+dy)*71 + ws;
                float v[14];
#pragma unroll
                for (int i2 = 0; i2 < 14; i2++) v[i2] = r[i2];
                unsigned long long pe[7], po[6];
#pragma unroll
                for (int j = 0; j < 7; j++) pe[j] = pack2(v[2*j],   v[2*j+1]);
#pragma unroll
                for (int j = 0; j < 6; j++) po[j] = pack2(v[2*j+1], v[2*j+2]);
                const float* wrow = c_w0 + (ci*7 + dy)*7;   // + o*98 + dx
#pragma unroll
                for (int dx = 0; dx < 7; dx++) {
#pragma unroll
                    for (int o = 0; o < 4; o++) {
                        float wv = wrow[o*98 + dx];
                        unsigned long long wp = pack2(wv, wv);
#pragma unroll
                        for (int k = 0; k < 4; k++) {
                            unsigned long long inp =
                                (dx & 1) ? po[(dx >> 1) + k] : pe[(dx >> 1) + k];
                            acc[o][k] = fma2(inp, wp, acc[o][k]);
                        }
                    }
                }
            }
        }
#pragma unroll
        for (int o = 0; o < 4; o++) {
            float res[8];
#pragma unroll
            for (int k = 0; k < 4; k++) unpack2(acc[o][k], res[2*k], res[2*k+1]);
            float4* dst = (float4*)(out + o*4096 + h*64 + ws);
            dst[0] = make_float4(res[0], res[1], res[2], res[3]);
            dst[1] = make_float4(res[4], res[5], res[6], res[7]);
        }
    }
}

// ---------------------------------------------------------------------------
// K1b: spike scan layer 1 (sequential t, per location) fused with 4x4 pooling.
// grid: 256 blocks = (n, o, 4-row group), 256 threads = 4 rows x 64 cols.
// v += u_t ; s = v>=1 ; v -= s   (== cumsum + IAF refractory, theta=1)
// ---------------------------------------------------------------------------
__global__ void __launch_bounds__(256) k1b_scan1() {
    const int b = blockIdx.x;
    const int n = b >> 6, o = (b >> 4) & 3, Hq = b & 15;
    const int tid = threadIdx.x;
    const int ty = tid >> 6, tx = tid & 63;
    const int h = Hq*4 + ty;

    const float* ub = g_u1 + ((size_t)(n*TT)*4 + o)*4096 + h*64 + tx;  // +t*16384
    float*       pb = g_p1 + ((size_t)(n*TT)*4 + o)*256  + Hq*16;      // +t*1024

    __shared__ float sb[2][256];
    float m = 0.f;
    float un = ub[0];
#pragma unroll 1
    for (int t = 0; t < TT; t++) {
        float u = un;
        if (t < TT-1) un = ub[(size_t)(t+1)*16384];
        m += u;
        float s = (m >= 1.f) ? 1.f : 0.f;
        m -= s;
        sb[t & 1][tid] = s;
        __syncthreads();
        if (tid < 16) {
            const float* q = &sb[t & 1][tid*4];
            float a = q[0]+q[1]+q[2]+q[3]
                    + q[64]+q[65]+q[66]+q[67]
                    + q[128]+q[129]+q[130]+q[131]
                    + q[192]+q[193]+q[194]+q[195];
            pb[(size_t)t*1024 + tid] = a * 0.0625f;
        }
    }
}

// ---------------------------------------------------------------------------
// K2a: conv2 4->8ch 7x7 pad3 on 16x16, one (n,t) slab per block, 128 threads.
// Each thread: 2 pixels (h, h+8) x 8 output channels. Weights from constant.
// ---------------------------------------------------------------------------
__global__ void __launch_bounds__(128) k2a_conv2() {
    const int b = blockIdx.x;              // n*100 + t
    __shared__ float pp[4*22*23];          // padded pooled input, stride 23

    for (int i = threadIdx.x; i < 4*22*23; i += 128) pp[i] = 0.f;
    __syncthreads();
    const float* slab = g_p1 + (size_t)b * 1024;
    for (int i = threadIdx.x; i < 1024; i += 128) {
        int ci = i >> 8, h = (i >> 4) & 15, w = i & 15;
        pp[ci*506 + (h+3)*23 + (w+3)] = slab[i];
    }
    __syncthreads();

    const int r = threadIdx.x;
    const int hA = r >> 4, w = r & 15;     // hB = hA + 8
    float accA[8], accB[8];
#pragma unroll
    for (int o = 0; o < 8; o++) { accA[o] = 0.f; accB[o] = 0.f; }

#pragma unroll 1
    for (int ci = 0; ci < 4; ci++) {
#pragma unroll 1
        for (int dy = 0; dy < 7; dy++) {
            const float* rowA = pp + ci*506 + (hA+dy)*23 + w;
            const float* rowB = rowA + 8*23;
            float a[7], bb[7];
#pragma unroll
            for (int i2 = 0; i2 < 7; i2++) { a[i2] = rowA[i2]; bb[i2] = rowB[i2]; }
            const float* wrow = c_w1 + (ci*7 + dy)*7;   // + o*196 + dx
#pragma unroll
            for (int dx = 0; dx < 7; dx++) {
#pragma unroll
                for (int o = 0; o < 8; o++) {
                    float wv = wrow[o*196 + dx];
                    accA[o] += a[dx]  * wv;
                    accB[o] += bb[dx] * wv;
                }
            }
        }
    }
    float* out = g_u2 + (size_t)b * 2048;
#pragma unroll
    for (int o = 0; o < 8; o++) {
        out[o*256 +  hA     *16 + w] = accA[o];
        out[o*256 + (hA + 8)*16 + w] = accB[o];
    }
}

// ---------------------------------------------------------------------------
// K2b: spike scan layer 2 -> s2 bytes. 32 blocks x 256 threads (8192 locations).
// ---------------------------------------------------------------------------
__global__ void __launch_bounds__(256) k2b_scan2() {
    const int g = blockIdx.x*256 + threadIdx.x;
    const int n = g >> 11, rest = g & 2047;
    const float* ub = g_u2 + (size_t)n*204800 + rest;   // +t*2048
    unsigned char* sp = g_s2 + (size_t)n*204800 + rest;
    float m = 0.f;
    float un = ub[0];
#pragma unroll 1
    for (int t = 0; t < TT; t++) {
        float u = un;
        if (t < TT-1) un = ub[(size_t)(t+1)*2048];
        m += u;
        float s = (m >= 1.f) ? 1.f : 0.f;
        m -= s;
        sp[(size_t)t*2048] = (unsigned char)s;
    }
}

// ---------------------------------------------------------------------------
// K3: 4x4 pool of s2 + einsum with wl -> out (n,2,t). 400 blocks x 64 threads.
// pooled einsum == direct sum over s2 with wl[o][c][h>>2][w>>2] / 16.
// ---------------------------------------------------------------------------
__global__ void __launch_bounds__(64) k3_out(float* __restrict__ out) {
    const int b = blockIdx.x;
    const int n = b / 100, t = b - n*100;
    const unsigned char* slab = g_s2 + (size_t)b * 2048;
    const int tid = threadIdx.x;
    float a0 = 0.f, a1 = 0.f;
    for (int i = tid; i < 2048; i += 64) {
        float s = (float)slab[i];
        int cc = i >> 8;
        int hh = (i >> 6) & 3;
        int ww = (i >> 2) & 3;
        int wi = (cc*4 + hh)*4 + ww;
        a0 += s * c_wl[wi];
        a1 += s * c_wl[128 + wi];
    }
    __shared__ float r0[64], r1[64];
    r0[tid] = a0; r1[tid] = a1;
    __syncthreads();
    if (tid < 32) {
        float v0 = r0[tid] + r0[tid+32];
        float v1 = r1[tid] + r1[tid+32];
#pragma unroll
        for (int off = 16; off > 0; off >>= 1) {
            v0 += __shfl_down_sync(0xffffffffu, v0, off);
            v1 += __shfl_down_sync(0xffffffffu, v1, off);
        }
        if (tid == 0) {
            out[(n*2 + 0)*100 + t] = v0 * 0.0625f;
            out[(n*2 + 1)*100 + t] = v1 * 0.0625f;
        }
    }
}

// ---------------------------------------------------------------------------
extern "C" void kernel_launch(void* const* d_in, const int* in_sizes, int n_in,
                              void* d_out, int out_size) {
    (void)in_sizes; (void)n_in; (void)out_size;
    const float* data = (const float*)d_in[0];

    cudaMemcpyToSymbolAsync(c_w0, d_in[1], sizeof(float)*392,  0,
                            cudaMemcpyDeviceToDevice, 0);
    cudaMemcpyToSymbolAsync(c_w1, d_in[2], sizeof(float)*1568, 0,
                            cudaMemcpyDeviceToDevice, 0);
    cudaMemcpyToSymbolAsync(c_wl, d_in[3], sizeof(float)*256,  0,
                            cudaMemcpyDeviceToDevice, 0);

    k0_pool  <<<512, 256>>>(data);
    k1a_conv1<<<400, 256>>>();
    k1b_scan1<<<256, 256>>>();
    k2a_conv2<<<400, 128>>>();
    k2b_scan2<<< 32, 256>>>();
    k3_out   <<<400,  64>>>((float*)d_out);
}

// round 2
// speedup vs baseline: 1.2150x; 1.2150x over previous
#include <cuda_runtime.h>
#include <cstdint>

// ---------------------------------------------------------------------------
// SLAYER SNN pipeline, t-major intermediates:
//   K0 : pool4 input (n,c,256,256,t) -> p0 (n,t,2,64,64)     [DRAM-bound floor]
//   K1a: conv1 7x7 pad3 (2->4) per (n,t) slab -> u1          [f32x2 FMA]
//   K1b: spike scan over t, pure recurrence -> s1 bytes      [no barriers]
//   K2a: dp4a 4x4 pool of s1 + conv2 (4->8) -> u2            [f32x2 oc-pairs]
//   K2b: spike scan over t -> s2 bytes                       [depth-4 prefetch]
//   K3 : dp4a pool + einsum wl -> out (n,2,t)
// ---------------------------------------------------------------------------

#define NB 4
#define TT 100

__device__ float g_p0[NB*TT*2*64*64];          // 3,276,800 floats
__device__ float g_u1[NB*TT*4*64*64];          // 6,553,600 floats
__device__ unsigned char g_s1[NB*TT*4*64*64];  // 6,553,600 bytes
__device__ float g_u2[NB*TT*8*16*16];          //   819,200 floats
__device__ unsigned char g_s2[NB*TT*8*16*16];  //   819,200 bytes

__constant__ float c_w0[4*2*7*7];    // 392
__constant__ float c_w1[8*4*7*7];    // 1568
__constant__ float c_wl[2*8*4*4];    // 256

// ---- packed f32x2 helpers (sm_100+) ----
__device__ __forceinline__ unsigned long long pack2(float lo, float hi) {
    unsigned long long r;
    asm("mov.b64 %0, {%1, %2};" : "=l"(r) : "f"(lo), "f"(hi));
    return r;
}
__device__ __forceinline__ void unpack2(unsigned long long v, float& lo, float& hi) {
    asm("mov.b64 {%0, %1}, %2;" : "=f"(lo), "=f"(hi) : "l"(v));
}
__device__ __forceinline__ unsigned long long fma2(unsigned long long a,
                                                   unsigned long long b,
                                                   unsigned long long c) {
    unsigned long long d;
    asm("fma.rn.f32x2 %0, %1, %2, %3;" : "=l"(d) : "l"(a), "l"(b), "l"(c));
    return d;
}
__device__ __forceinline__ int dp4a_sum(unsigned int u, int acc) {
    int r;
    asm("dp4a.u32.u32 %0, %1, %2, %3;" : "=r"(r)
        : "r"(u), "r"(0x01010101u), "r"(acc));
    return r;
}

// ---------------------------------------------------------------------------
// K0: 4x4 average pool of raw input with layout transpose to t-major.
// 512 blocks = (n,c,H64), 256 threads. Reads 210MB coalesced (float4 over t).
// ---------------------------------------------------------------------------
__global__ void __launch_bounds__(256) k0_pool(const float* __restrict__ in) {
    const int b = blockIdx.x;
    const int n = b >> 7, c = (b >> 6) & 1, H = b & 63;
    __shared__ float sm[TT][65];   // [t][W]

    const float* base = in + (size_t)((n*2 + c)*256 + H*4) * 25600;

    for (int idx = threadIdx.x; idx < 1600; idx += 256) {
        int W  = idx / 25;
        int tq = idx - W*25;           // t-quad 0..24
        const float4* p = (const float4*)(base + (size_t)(W*4)*100 + tq*4);
        float4 s = make_float4(0.f, 0.f, 0.f, 0.f);
#pragma unroll
        for (int dy = 0; dy < 4; dy++)
#pragma unroll
            for (int dx = 0; dx < 4; dx++) {
                float4 v = p[dy*6400 + dx*25];
                s.x += v.x; s.y += v.y; s.z += v.z; s.w += v.w;
            }
        int t = tq*4;
        sm[t+0][W] = s.x*0.0625f; sm[t+1][W] = s.y*0.0625f;
        sm[t+2][W] = s.z*0.0625f; sm[t+3][W] = s.w*0.0625f;
    }
    __syncthreads();
    const size_t ob = ((size_t)(n*TT)*2 + c)*4096 + H*64;
    for (int idx = threadIdx.x; idx < 6400; idx += 256) {
        int t = idx >> 6, W = idx & 63;
        g_p0[ob + (size_t)t*8192 + W] = sm[t][W];
    }
}

// ---------------------------------------------------------------------------
// K1a: conv1 2->4ch 7x7 pad3 on 64x64, one (n,t) slab per block, 256 threads.
// f32x2: 2 output pixels per FMA, weight dup-pack amortized over 4 segments.
// ---------------------------------------------------------------------------
__global__ void __launch_bounds__(256, 2) k1a_conv1() {
    const int b = blockIdx.x;              // n*100 + t
    __shared__ float si[2*70*71];          // zero-padded input, stride 71

    for (int i = threadIdx.x; i < 2*70*71; i += 256) si[i] = 0.f;
    __syncthreads();
    const float* slab = g_p0 + (size_t)b * 8192;
    for (int i = threadIdx.x; i < 8192; i += 256) {
        int ci = i >> 12, h = (i >> 6) & 63, w = i & 63;
        si[ci*4970 + (h+3)*71 + (w+3)] = slab[i];
    }
    __syncthreads();

    float* out = g_u1 + (size_t)b * 16384;

#pragma unroll 1
    for (int rep = 0; rep < 2; rep++) {
        const int pos = threadIdx.x + (rep << 8);   // 0..511
        const int h  = pos >> 3;
        const int ws = (pos & 7) << 3;              // 8-pixel segment start
        unsigned long long acc[4][4];
#pragma unroll
        for (int o = 0; o < 4; o++)
#pragma unroll
            for (int k = 0; k < 4; k++) acc[o][k] = 0ull;

#pragma unroll 1
        for (int ci = 0; ci < 2; ci++) {
#pragma unroll 1
            for (int dy = 0; dy < 7; dy++) {
                const float* r = si + ci*4970 + (h+dy)*71 + ws;
                float v[14];
#pragma unroll
                for (int i2 = 0; i2 < 14; i2++) v[i2] = r[i2];
                unsigned long long pe[7], po[6];
#pragma unroll
                for (int j = 0; j < 7; j++) pe[j] = pack2(v[2*j],   v[2*j+1]);
#pragma unroll
                for (int j = 0; j < 6; j++) po[j] = pack2(v[2*j+1], v[2*j+2]);
                const float* wrow = c_w0 + (ci*7 + dy)*7;   // + o*98 + dx
#pragma unroll
                for (int dx = 0; dx < 7; dx++) {
#pragma unroll
                    for (int o = 0; o < 4; o++) {
                        float wv = wrow[o*98 + dx];
                        unsigned long long wp = pack2(wv, wv);
#pragma unroll
                        for (int k = 0; k < 4; k++) {
                            unsigned long long inp =
                                (dx & 1) ? po[(dx >> 1) + k] : pe[(dx >> 1) + k];
                            acc[o][k] = fma2(inp, wp, acc[o][k]);
                        }
                    }
                }
            }
        }
#pragma unroll
        for (int o = 0; o < 4; o++) {
            float res[8];
#pragma unroll
            for (int k = 0; k < 4; k++) unpack2(acc[o][k], res[2*k], res[2*k+1]);
            float4* dst = (float4*)(out + o*4096 + h*64 + ws);
            dst[0] = make_float4(res[0], res[1], res[2], res[3]);
            dst[1] = make_float4(res[4], res[5], res[6], res[7]);
        }
    }
}

// ---------------------------------------------------------------------------
// K1b: spike scan layer 1 — pure per-thread recurrence, no barriers.
// 16384 threads, each owns 4 adjacent w-locations (float4 in, uchar4 out),
// depth-4 temporal prefetch to keep 4 loads in flight.
// ---------------------------------------------------------------------------
__global__ void __launch_bounds__(128) k1b_scan1() {
    const int g = blockIdx.x*128 + threadIdx.x;     // 0..16383
    const int n = g >> 12, r = g & 4095;            // r: (c,h,wq) 4*64*16
    const float4* ub = (const float4*)g_u1 + (size_t)(n*TT)*4096 + r;  // +t*4096
    uchar4* sp = (uchar4*)g_s1 + (size_t)(n*TT)*4096 + r;              // +t*4096

    float m0 = 0.f, m1 = 0.f, m2 = 0.f, m3 = 0.f;
    float4 buf[4];
#pragma unroll
    for (int i = 0; i < 4; i++) buf[i] = ub[(size_t)i*4096];

#pragma unroll 1
    for (int tg = 0; tg < 25; tg++) {
        float4 c0 = buf[0], c1 = buf[1], c2 = buf[2], c3 = buf[3];
        if (tg < 24) {
#pragma unroll
            for (int i = 0; i < 4; i++)
                buf[i] = ub[(size_t)(tg*4 + 4 + i)*4096];
        }
#pragma unroll
        for (int i = 0; i < 4; i++) {
            float4 c = (i == 0) ? c0 : (i == 1) ? c1 : (i == 2) ? c2 : c3;
            m0 += c.x; float s0 = (m0 >= 1.f) ? 1.f : 0.f; m0 -= s0;
            m1 += c.y; float s1 = (m1 >= 1.f) ? 1.f : 0.f; m1 -= s1;
            m2 += c.z; float s2 = (m2 >= 1.f) ? 1.f : 0.f; m2 -= s2;
            m3 += c.w; float s3 = (m3 >= 1.f) ? 1.f : 0.f; m3 -= s3;
            sp[(size_t)(tg*4 + i)*4096] =
                make_uchar4((unsigned char)s0, (unsigned char)s1,
                            (unsigned char)s2, (unsigned char)s3);
        }
    }
}

// ---------------------------------------------------------------------------
// K2a: dp4a 4x4 pool of s1 bytes + conv2 4->8ch 7x7 pad3 on 16x16.
// One (n,t) slab per block, 256 threads = 1 pixel x 8 oc each.
// f32x2 over output-channel pairs; packed weight pairs staged in smem
// (warp-uniform broadcast LDS.64), input dup-mov amortized over 4 fma2.
// ---------------------------------------------------------------------------
__global__ void __launch_bounds__(256) k2a_conv2() {
    const int b = blockIdx.x;              // n*100 + t
    __shared__ float pp[4*22*23];          // padded pooled input, stride 23
    __shared__ unsigned long long wdup[4*196];  // [p][ci*49+dy*7+dx], oc pair p

    for (int i = threadIdx.x; i < 4*22*23; i += 256) pp[i] = 0.f;
    for (int i = threadIdx.x; i < 784; i += 256) {
        int p = i / 196, q = i - p*196;
        wdup[i] = pack2(c_w1[(2*p)*196 + q], c_w1[(2*p+1)*196 + q]);
    }
    __syncthreads();

    // pool: 1024 pooled values, each = dp4a over 4 rows of 4 spike bytes
    const unsigned char* sslab = g_s1 + (size_t)b * 16384;
    for (int i = threadIdx.x; i < 1024; i += 256) {
        int ci = i >> 8, ph = (i >> 4) & 15, pw = i & 15;
        const unsigned int* srow =
            (const unsigned int*)(sslab + ci*4096 + ph*256) + pw;  // row = 16 uints
        int s = 0;
#pragma unroll
        for (int rr = 0; rr < 4; rr++) s = dp4a_sum(srow[rr*16], s);
        pp[ci*506 + (ph+3)*23 + (pw+3)] = (float)s * 0.0625f;
    }
    __syncthreads();

    const int h = threadIdx.x >> 4, w = threadIdx.x & 15;
    unsigned long long acc2[4];
#pragma unroll
    for (int p = 0; p < 4; p++) acc2[p] = 0ull;

#pragma unroll 1
    for (int ci = 0; ci < 4; ci++) {
#pragma unroll 1
        for (int dy = 0; dy < 7; dy++) {
            const float* row = pp + ci*506 + (h+dy)*23 + w;
            float a[7];
#pragma unroll
            for (int i2 = 0; i2 < 7; i2++) a[i2] = row[i2];
            const unsigned long long* wr = wdup + ci*49 + dy*7;
#pragma unroll
            for (int dx = 0; dx < 7; dx++) {
                unsigned long long ap = pack2(a[dx], a[dx]);
#pragma unroll
                for (int p = 0; p < 4; p++)
                    acc2[p] = fma2(ap, wr[p*196 + dx], acc2[p]);
            }
        }
    }
    float* out = g_u2 + (size_t)b * 2048;
#pragma unroll
    for (int p = 0; p < 4; p++) {
        float r0, r1;
        unpack2(acc2[p], r0, r1);
        out[(2*p  )*256 + h*16 + w] = r0;
        out[(2*p+1)*256 + h*16 + w] = r1;
    }
}

// ---------------------------------------------------------------------------
// K2b: spike scan layer 2 -> s2 bytes. 8192 threads, depth-4 prefetch.
// ---------------------------------------------------------------------------
__global__ void __launch_bounds__(128) k2b_scan2() {
    const int g = blockIdx.x*128 + threadIdx.x;     // 0..8191
    const int n = g >> 11, r = g & 2047;
    const float* ub = g_u2 + (size_t)(n*TT)*2048 + r;     // +t*2048
    unsigned char* sp = g_s2 + (size_t)(n*TT)*2048 + r;

    float m = 0.f;
    float buf[4];
#pragma unroll
    for (int i = 0; i < 4; i++) buf[i] = ub[(size_t)i*2048];

#pragma unroll 1
    for (int tg = 0; tg < 25; tg++) {
        float c0 = buf[0], c1 = buf[1], c2 = buf[2], c3 = buf[3];
        if (tg < 24) {
#pragma unroll
            for (int i = 0; i < 4; i++)
                buf[i] = ub[(size_t)(tg*4 + 4 + i)*2048];
        }
        float cc[4] = {c0, c1, c2, c3};
#pragma unroll
        for (int i = 0; i < 4; i++) {
            m += cc[i];
            float s = (m >= 1.f) ? 1.f : 0.f;
            m -= s;
            sp[(size_t)(tg*4 + i)*2048] = (unsigned char)s;
        }
    }
}

// ---------------------------------------------------------------------------
// K3: dp4a pool of s2 + einsum with wl -> out (n,2,t). 400 blocks x 64 thr.
// Within a uint (4 consecutive w), the pooled weight index is constant.
// ---------------------------------------------------------------------------
__global__ void __launch_bounds__(64) k3_out(float* __restrict__ out) {
    const int b = blockIdx.x;
    const int n = b / 100, t = b - n*100;
    const unsigned int* slab = (const unsigned int*)(g_s2 + (size_t)b * 2048);
    const int tid = threadIdx.x;
    float a0 = 0.f, a1 = 0.f;
    for (int i = tid; i < 512; i += 64) {
        int cnt = dp4a_sum(slab[i], 0);
        int cc = i >> 6;
        int hh = (i >> 2) & 15;
        int wq = i & 3;
        int wi = cc*16 + (hh >> 2)*4 + wq;
        float f = (float)cnt;
        a0 += f * c_wl[wi];
        a1 += f * c_wl[128 + wi];
    }
    __shared__ float r0[64], r1[64];
    r0[tid] = a0; r1[tid] = a1;
    __syncthreads();
    if (tid < 32) {
        float v0 = r0[tid] + r0[tid+32];
        float v1 = r1[tid] + r1[tid+32];
#pragma unroll
        for (int off = 16; off > 0; off >>= 1) {
            v0 += __shfl_down_sync(0xffffffffu, v0, off);
            v1 += __shfl_down_sync(0xffffffffu, v1, off);
        }
        if (tid == 0) {
            out[(n*2 + 0)*100 + t] = v0 * 0.0625f;
            out[(n*2 + 1)*100 + t] = v1 * 0.0625f;
        }
    }
}

// ---------------------------------------------------------------------------
extern "C" void kernel_launch(void* const* d_in, const int* in_sizes, int n_in,
                              void* d_out, int out_size) {
    (void)in_sizes; (void)n_in; (void)out_size;
    const float* data = (const float*)d_in[0];

    cudaMemcpyToSymbolAsync(c_w0, d_in[1], sizeof(float)*392,  0,
                            cudaMemcpyDeviceToDevice, 0);
    cudaMemcpyToSymbolAsync(c_w1, d_in[2], sizeof(float)*1568, 0,
                            cudaMemcpyDeviceToDevice, 0);
    cudaMemcpyToSymbolAsync(c_wl, d_in[3], sizeof(float)*256,  0,
                            cudaMemcpyDeviceToDevice, 0);

    k0_pool  <<<512, 256>>>(data);
    k1a_conv1<<<400, 256>>>();
    k1b_scan1<<<128, 128>>>();
    k2a_conv2<<<400, 256>>>();
    k2b_scan2<<< 64, 128>>>();
    k3_out   <<<400,  64>>>((float*)d_out);
}